// round 13
// baseline (speedup 1.0000x reference)
#include <cuda_runtime.h>
#include <cuda_fp16.h>
#include <cstdint>

#define Bb 8
#define Nn 2048
#define ALPHA 0.2f

// ---------------- device globals (no allocation allowed) -------------------
__device__ float    g_s[Bb * Nn];
__device__ float    g_t[Bb * Nn];
__device__ float    g_tmax[Bb];
__device__ __half   g_WhT[Bb * 64 * Nn];       // [b][f][j], fp16, 2MB
__device__ uint32_t g_adjbits[Bb * Nn * 64];   // adj bit-packed, 4MB

// ---------------- PTX helpers ----------------------------------------------
__device__ __forceinline__ uint32_t su32(const void* p) {
    uint32_t a;
    asm("{ .reg .u64 t; cvta.to.shared.u64 t, %1; cvt.u32.u64 %0, t; }"
        : "=r"(a) : "l"(p));
    return a;
}
#define CVTH2(r, lo, hi) \
    asm("cvt.rn.f16x2.f32 %0, %2, %1;" : "=r"(r) : "f"(lo), "f"(hi))
#define HMUL2(r, a, b) \
    asm("mul.f16x2 %0, %1, %2;" : "=r"(r) : "r"(a), "r"(b))
#define HMAX2(r, a, b) \
    asm("max.f16x2 %0, %1, %2;" : "=r"(r) : "r"(a), "r"(b))

#define LDSM4(r0, r1, r2, r3, addr) \
    asm volatile("ldmatrix.sync.aligned.m8n8.x4.shared.b16 {%0,%1,%2,%3}, [%4];" \
                 : "=r"(r0), "=r"(r1), "=r"(r2), "=r"(r3) : "r"(addr))

#define MMA16816(dd, a0, a1, a2, a3, b0, b1) \
    asm volatile("mma.sync.aligned.m16n8k16.row.col.f32.f16.f16.f32 " \
                 "{%0,%1,%2,%3}, {%4,%5,%6,%7}, {%8,%9}, {%0,%1,%2,%3};" \
                 : "+f"((dd)[0]), "+f"((dd)[1]), "+f"((dd)[2]), "+f"((dd)[3]) \
                 : "r"(a0), "r"(a1), "r"(a2), "r"(a3), "r"(b0), "r"(b1))

#define CP16(dst, src) \
    asm volatile("cp.async.cg.shared.global [%0], [%1], 16;" \
                 :: "r"(dst), "l"(src) : "memory")
#define CP_COMMIT() asm volatile("cp.async.commit_group;" ::: "memory")
#define CP_WAIT1()  asm volatile("cp.async.wait_group 1;" ::: "memory")
#define BARG(id) \
    asm volatile("bar.sync %0, 128;" :: "r"(id) : "memory")

// ---------------------------------------------------------------------------
// Kernel PA: fused. Blocks 0..1023: Wh = h@W (16 rows each), s, t, WhT emit.
// Blocks 1024..3071: adj bit-packing via warp ballots (streaming __ldcs).
// ---------------------------------------------------------------------------
__global__ void __launch_bounds__(256) kPA(const float* __restrict__ h,
                                           const float* __restrict__ W,
                                           const float* __restrict__ a,
                                           const int* __restrict__ adj) {
    __shared__ float  Wsh[64 * 64];
    __shared__ float  hsh[16][64];
    __shared__ float  red[16][2][2];
    __shared__ __half Tsh[64][20];

    int t = threadIdx.x;
    int lane = t & 31;

    if (blockIdx.x >= 1024) {           // ---- kP part ----
        int vb = blockIdx.x - 1024;
        int nw = 2048 * 8;
        int gw = vb * 8 + (t >> 5);
        const size_t total = (size_t)Bb * Nn * Nn;
        for (size_t base = (size_t)gw * 128; base < total;
             base += (size_t)nw * 128) {
            int v0 = __ldcs(adj + base + lane);
            int v1 = __ldcs(adj + base + 32 + lane);
            int v2 = __ldcs(adj + base + 64 + lane);
            int v3 = __ldcs(adj + base + 96 + lane);
            uint32_t b0 = __ballot_sync(0xffffffffu, v0 > 0);
            uint32_t b1 = __ballot_sync(0xffffffffu, v1 > 0);
            uint32_t b2 = __ballot_sync(0xffffffffu, v2 > 0);
            uint32_t b3 = __ballot_sync(0xffffffffu, v3 > 0);
            if (lane == 0)
                *(uint4*)(g_adjbits + base / 32) = make_uint4(b0, b1, b2, b3);
        }
        return;
    }

    // ---- kA part: 16 rows per block ----
    int o = t & 63, rg = t >> 6;
    int hw = (t >> 5) & 1;
    int blk = blockIdx.x;

#pragma unroll
    for (int k = 0; k < 16; k++) Wsh[t + 256 * k] = W[t + 256 * k];
    float a1 = a[o], a2 = a[64 + o];

    {
        int rr = t >> 4, f4 = t & 15;
        *(float4*)&hsh[rr][f4 * 4] =
            *(const float4*)(h + (size_t)(blk * 16 + rr) * 64 + f4 * 4);
    }
    __syncthreads();

    float acc[4] = {0.f, 0.f, 0.f, 0.f};
#pragma unroll
    for (int f4 = 0; f4 < 16; f4++) {
        float w0 = Wsh[(f4 * 4 + 0) * 64 + o];
        float w1 = Wsh[(f4 * 4 + 1) * 64 + o];
        float w2 = Wsh[(f4 * 4 + 2) * 64 + o];
        float w3 = Wsh[(f4 * 4 + 3) * 64 + o];
#pragma unroll
        for (int r = 0; r < 4; r++) {
            float4 hv = *(const float4*)&hsh[rg * 4 + r][f4 * 4];
            acc[r] += hv.x * w0 + hv.y * w1 + hv.z * w2 + hv.w * w3;
        }
    }
    int jloc = rg * 4;
    *(half2*)&Tsh[o][jloc]     = __floats2half2_rn(acc[0], acc[1]);
    *(half2*)&Tsh[o][jloc + 2] = __floats2half2_rn(acc[2], acc[3]);

#pragma unroll
    for (int r = 0; r < 4; r++) {
        float sv = acc[r] * a1;
        float tv = acc[r] * a2;
#pragma unroll
        for (int off = 16; off; off >>= 1) {
            sv += __shfl_down_sync(0xffffffffu, sv, off);
            tv += __shfl_down_sync(0xffffffffu, tv, off);
        }
        if (lane == 0) { red[rg * 4 + r][hw][0] = sv; red[rg * 4 + r][hw][1] = tv; }
    }
    __syncthreads();
    if (t < 16) {
        int row = blk * 16 + t;
        g_s[row] = red[t][0][0] + red[t][1][0];
        g_t[row] = red[t][0][1] + red[t][1][1];
    }
    {   // WhT tile: 64 f-rows x 16 j (uint2 = 8B per thread)
        int f = t >> 2, c = t & 3;
        uint2 v = *(const uint2*)&Tsh[f][c * 4];
        int b  = (blk * 16) >> 11;
        int j0 = (blk * 16) & 2047;
        *(uint2*)(g_WhT + (size_t)(b * 64 + f) * Nn + j0 + c * 4) = v;
    }
}

// ---------------------------------------------------------------------------
// Kernel B: per-batch tmax
// ---------------------------------------------------------------------------
__global__ void __launch_bounds__(256) kB() {
    __shared__ float red[256];
    int b = blockIdx.x, t = threadIdx.x;
    float m = -1e30f;
#pragma unroll
    for (int k = 0; k < 8; k++) m = fmaxf(m, g_t[b * Nn + t + 256 * k]);
    red[t] = m;
    __syncthreads();
#pragma unroll
    for (int s = 128; s; s >>= 1) {
        if (t < s) red[t] = fmaxf(red[t], red[t + s]);
        __syncthreads();
    }
    if (t == 0) g_tmax[b] = red[0];
}

// ---------------------------------------------------------------------------
// Kernel D: fused masked softmax + HMMA P@Wh + ELU, bit-packed adj.
// 256 thr = 2 groups of 4 warps; 64-row i-tiles; grid (32,8)=256 blocks ->
// 3 blocks/SM (24 warps/SM). Group g handles j-tiles [g*16, g*16+16) with
// its own cp.async triple buffer + named barrier. Phase-1 in f16x2; row
// sums via ones-MMA. Group-1 deposit buffer ALIASES its dead Wh buffers.
// ---------------------------------------------------------------------------
#define PSTR     72                      // wsh row stride in halves (144B)
#define WTILE_B  (64 * PSTR * 2)         // 9216 bytes per Wh buffer
#define OFF_WSH  0                       // 2 groups x 3 buffers = 55296
#define OFF_CT   55296                   // 1024 x uint2 = 8192
#define OFF_SA   63488                   // 64 f32
#define OFF_SAP  63744                   // 64 f32
#define OFF_RS0  64000                   // 64 f32
#define OFF_RS1  64256                   // 64 f32
#define OFF_CB   (3 * WTILE_B)           // aliases group-1 wsh (16KB <= 27.6KB)
#define SMEM_TOT 64512
#define ONE2     0x3C003C00u

__global__ void __launch_bounds__(256, 3) kD(float* __restrict__ out) {
    extern __shared__ char sm[];
    __half* wsh  = (__half*)(sm + OFF_WSH);
    uint2*  cT   = (uint2*)(sm + OFF_CT);
    float*  sAs  = (float*)(sm + OFF_SA);
    float*  sAps = (float*)(sm + OFF_SAP);
    float*  rs0  = (float*)(sm + OFF_RS0);
    float*  rs1  = (float*)(sm + OFF_RS1);
    float*  cbuf = (float*)(sm + OFF_CB);

    int t = threadIdx.x, lane = t & 31;
    int g = t >> 7;                      // warp-group 0/1 (4 warps each)
    int tl = t & 127;
    int w = (t >> 5) & 3;                // warp within group
    int b = blockIdx.y, i0 = blockIdx.x * 64;

    int lr0 = w * 16 + (lane >> 2), lr1 = lr0 + 8;   // local rows 0..63
    int c2 = (lane & 3) * 2;
    const uint32_t* bits0 = g_adjbits + (size_t)(b * Nn + i0 + lr0) * 64;
    const uint32_t* bits1 = g_adjbits + (size_t)(b * Nn + i0 + lr1) * 64;
    const __half* whb = g_WhT + (size_t)b * 64 * Nn;
    uint32_t wsh_u = su32(wsh);
    int k0 = g * 16;

#define ISSUE_WH(k) do {                                                    \
    int _buf = g * 3 + (k) % 3;                                             \
    int _f = tl >> 1, _hf = tl & 1;                                         \
    const __half* _s0 = whb + (size_t)_f * Nn + (k) * 64 + _hf * 32;        \
    uint32_t _d0 = wsh_u + _buf * WTILE_B + _f * (PSTR * 2) + _hf * 64;     \
    CP16(_d0,      _s0);                                                    \
    CP16(_d0 + 16, _s0 + 8);                                                \
    CP16(_d0 + 32, _s0 + 16);                                               \
    CP16(_d0 + 48, _s0 + 24);                                               \
    CP_COMMIT(); } while (0)

    ISSUE_WH(k0);
    ISSUE_WH(k0 + 1);

    // interleaved f16x2 exp tables: cT[j/2] = { half2(B,B+1), half2(C,C+1) }
    float tmax = g_tmax[b];
#pragma unroll
    for (int q = 0; q < 4; q++) {
        int idx = t + 256 * q;           // 0..1023
        int j = idx * 2;
        float d0 = g_t[b * Nn + j] - tmax;
        float d1 = g_t[b * Nn + j + 1] - tmax;
        float B0 = __expf(d0), B1 = __expf(d1);
        float C0 = __expf(ALPHA * d0), C1 = __expf(ALPHA * d1);
        uint32_t b2, cc2;
        CVTH2(b2, B0, B1);
        CVTH2(cc2, C0, C1);
        cT[idx] = make_uint2(b2, cc2);
    }
    if (t < 64) {
        float x = g_s[b * Nn + i0 + t] + tmax;
        float m = fmaxf(x, ALPHA * x);
        sAs[t]  = __expf(x - m);
        sAps[t] = __expf(ALPHA * x - m);
    }
    __syncthreads();

    uint32_t Ai0_2, Ap0_2, Ai1_2, Ap1_2;
    {
        float v;
        v = sAs[lr0];  CVTH2(Ai0_2, v, v);
        v = sAps[lr0]; CVTH2(Ap0_2, v, v);
        v = sAs[lr1];  CVTH2(Ai1_2, v, v);
        v = sAps[lr1]; CVTH2(Ap1_2, v, v);
    }

    int mi = lane >> 3, r8 = lane & 7;
    uint32_t b_row_off = ((mi >> 1) * 8 + r8) * (PSTR * 2) + (mi & 1) * 16;

    float d[8][4];
#pragma unroll
    for (int nb = 0; nb < 8; nb++)
#pragma unroll
        for (int q = 0; q < 4; q++) d[nb][q] = 0.f;
    float dsum[4] = {0.f, 0.f, 0.f, 0.f};

    uint2 awc0 = *(const uint2*)(bits0 + k0 * 2);
    uint2 awc1 = *(const uint2*)(bits1 + k0 * 2);
    uint2 awn0, awn1;

    for (int kk = 0; kk < 16; kk++) {
        int k = k0 + kk;
        CP_WAIT1();
        BARG(1 + g);
        if (kk < 15) {
            awn0 = *(const uint2*)(bits0 + (k + 1) * 2);
            awn1 = *(const uint2*)(bits1 + (k + 1) * 2);
        }
        uint32_t wb = wsh_u + (g * 3 + k % 3) * WTILE_B;
#pragma unroll
        for (int kc = 0; kc < 4; kc++) {
            uint32_t wA = (kc & 2) ? awc0.y : awc0.x;
            uint32_t wB = (kc & 2) ? awc1.y : awc1.x;
            int sh = ((kc & 1) << 4) + c2;
            int idx = (k * 64 + kc * 16 + c2) >> 1;
            uint2 u0 = cT[idx];          // pair (j, j+1)
            uint2 u1 = cT[idx + 4];      // pair (j+8, j+9)

            uint32_t ia0 = (wA >> sh) & 3u;
            uint32_t ia1 = (wA >> (sh + 8)) & 3u;
            uint32_t ib0 = (wB >> sh) & 3u;
            uint32_t ib1 = (wB >> (sh + 8)) & 3u;
            uint32_t mA0 = ((ia0 & 1u) ? 0x0000FFFFu : 0u) | ((ia0 & 2u) ? 0xFFFF0000u : 0u);
            uint32_t mA1 = ((ia1 & 1u) ? 0x0000FFFFu : 0u) | ((ia1 & 2u) ? 0xFFFF0000u : 0u);
            uint32_t mB0 = ((ib0 & 1u) ? 0x0000FFFFu : 0u) | ((ib0 & 2u) ? 0xFFFF0000u : 0u);
            uint32_t mB1 = ((ib1 & 1u) ? 0x0000FFFFu : 0u) | ((ib1 & 2u) ? 0xFFFF0000u : 0u);

            uint32_t x0, x1, fa0, fa1, fa2, fa3;
            HMUL2(x0, Ai0_2, u0.x); HMUL2(x1, Ap0_2, u0.y); HMAX2(fa0, x0, x1);
            HMUL2(x0, Ai1_2, u0.x); HMUL2(x1, Ap1_2, u0.y); HMAX2(fa1, x0, x1);
            HMUL2(x0, Ai0_2, u1.x); HMUL2(x1, Ap0_2, u1.y); HMAX2(fa2, x0, x1);
            HMUL2(x0, Ai1_2, u1.x); HMUL2(x1, Ap1_2, u1.y); HMAX2(fa3, x0, x1);
            fa0 &= mA0; fa1 &= mB0; fa2 &= mA1; fa3 &= mB1;

            MMA16816(dsum, fa0, fa1, fa2, fa3, ONE2, ONE2);
#pragma unroll
            for (int nbp = 0; nbp < 4; nbp++) {
                uint32_t q0, q1, q2, q3;
                LDSM4(q0, q1, q2, q3,
                      wb + nbp * 16 * (PSTR * 2) + b_row_off + kc * 32);
                MMA16816(d[nbp * 2],     fa0, fa1, fa2, fa3, q0, q1);
                MMA16816(d[nbp * 2 + 1], fa0, fa1, fa2, fa3, q2, q3);
            }
        }
        awc0 = awn0; awc1 = awn1;
        if (kk < 14) ISSUE_WH(k + 2);
        else CP_COMMIT();
    }

    // intra-group barrier: all group warps done reading wsh before any alias
    BARG(1 + g);

    // row sums from the ones-MMA: dsum[0] = row lr0, dsum[2] = row lr1
    float* rsg = g ? rs1 : rs0;
    if ((lane & 3) == 0) {
        rsg[lr0] = dsum[0];
        rsg[lr1] = dsum[2];
    }
    if (g) {
#pragma unroll
        for (int nb = 0; nb < 8; nb++)
#pragma unroll
            for (int q = 0; q < 4; q++)
                cbuf[(nb * 4 + q) * 128 + tl] = d[nb][q];
    }
    __syncthreads();

    if (g == 0) {
        float l0 = 1.0f / (rs0[lr0] + rs1[lr0]);
        float l1 = 1.0f / (rs0[lr1] + rs1[lr1]);
        float* o0 = out + (size_t)(b * Nn + i0 + lr0) * 64 + c2;
        float* o1 = out + (size_t)(b * Nn + i0 + lr1) * 64 + c2;
#pragma unroll
        for (int nb = 0; nb < 8; nb++) {
            float x0 = (d[nb][0] + cbuf[(nb * 4 + 0) * 128 + tl]) * l0;
            float x1 = (d[nb][1] + cbuf[(nb * 4 + 1) * 128 + tl]) * l0;
            float y0 = (d[nb][2] + cbuf[(nb * 4 + 2) * 128 + tl]) * l1;
            float y1 = (d[nb][3] + cbuf[(nb * 4 + 3) * 128 + tl]) * l1;
            float2 v0, v1;
            v0.x = x0 > 0.f ? x0 : expm1f(x0);
            v0.y = x1 > 0.f ? x1 : expm1f(x1);
            v1.x = y0 > 0.f ? y0 : expm1f(y0);
            v1.y = y1 > 0.f ? y1 : expm1f(y1);
            *(float2*)(o0 + nb * 8) = v0;
            *(float2*)(o1 + nb * 8) = v1;
        }
    }
}

// ---------------------------------------------------------------------------
extern "C" void kernel_launch(void* const* d_in, const int* in_sizes, int n_in,
                              void* d_out, int out_size) {
    const float* h   = (const float*)d_in[0];   // (8,2048,64) f32
    const int*   adj = (const int*)d_in[1];     // (8,2048,2048) i32
    const float* W   = (const float*)d_in[2];   // (64,64) f32
    const float* a   = (const float*)d_in[3];   // (128,1) f32
    float* out = (float*)d_out;                 // (8,2048,64) f32

    cudaFuncSetAttribute(kD, cudaFuncAttributeMaxDynamicSharedMemorySize, SMEM_TOT);

    kPA<<<3072, 256>>>(h, W, a, adj);
    kB<<<Bb, 256>>>();
    kD<<<dim3(Nn / 64, Bb), 256, SMEM_TOT>>>(out);
}

// round 14
// speedup vs baseline: 1.1012x; 1.1012x over previous
#include <cuda_runtime.h>
#include <cuda_fp16.h>
#include <cstdint>

#define Bb 8
#define Nn 2048
#define ALPHA 0.2f

// ---------------- device globals (no allocation allowed) -------------------
__device__ float    g_s[Bb * Nn];
__device__ float    g_t[Bb * Nn];
__device__ float    g_tmax[Bb];
__device__ __half   g_WhT[Bb * 64 * Nn];       // [b][f][j], fp16, 2MB
__device__ uint32_t g_adjbits[Bb * Nn * 64];   // adj bit-packed, 4MB

// ---------------- PTX helpers ----------------------------------------------
__device__ __forceinline__ uint32_t su32(const void* p) {
    uint32_t a;
    asm("{ .reg .u64 t; cvta.to.shared.u64 t, %1; cvt.u32.u64 %0, t; }"
        : "=r"(a) : "l"(p));
    return a;
}
#define CVTH2(r, lo, hi) \
    asm("cvt.rn.f16x2.f32 %0, %2, %1;" : "=r"(r) : "f"(lo), "f"(hi))
#define HMUL2(r, a, b) \
    asm("mul.f16x2 %0, %1, %2;" : "=r"(r) : "r"(a), "r"(b))
#define HMAX2(r, a, b) \
    asm("max.f16x2 %0, %1, %2;" : "=r"(r) : "r"(a), "r"(b))

#define LDSM4(r0, r1, r2, r3, addr) \
    asm volatile("ldmatrix.sync.aligned.m8n8.x4.shared.b16 {%0,%1,%2,%3}, [%4];" \
                 : "=r"(r0), "=r"(r1), "=r"(r2), "=r"(r3) : "r"(addr))

#define MMA16816(dd, a0, a1, a2, a3, b0, b1) \
    asm volatile("mma.sync.aligned.m16n8k16.row.col.f32.f16.f16.f32 " \
                 "{%0,%1,%2,%3}, {%4,%5,%6,%7}, {%8,%9}, {%0,%1,%2,%3};" \
                 : "+f"((dd)[0]), "+f"((dd)[1]), "+f"((dd)[2]), "+f"((dd)[3]) \
                 : "r"(a0), "r"(a1), "r"(a2), "r"(a3), "r"(b0), "r"(b1))

#define CP16(dst, src) \
    asm volatile("cp.async.cg.shared.global [%0], [%1], 16;" \
                 :: "r"(dst), "l"(src) : "memory")
#define CP_COMMIT() asm volatile("cp.async.commit_group;" ::: "memory")
#define CP_WAIT1()  asm volatile("cp.async.wait_group 1;" ::: "memory")
#define BARG(id) \
    asm volatile("bar.sync %0, 256;" :: "r"(id) : "memory")

// ---------------------------------------------------------------------------
// Kernel PA (R12 exact): blocks 0..511 do Wh=h@W (32 rows each) + s,t + WhT;
// blocks 512..2559 bit-pack adj via warp ballots.
// ---------------------------------------------------------------------------
__global__ void __launch_bounds__(256) kPA(const float* __restrict__ h,
                                           const float* __restrict__ W,
                                           const float* __restrict__ a,
                                           const int* __restrict__ adj) {
    __shared__ float  Wsh[64 * 64];
    __shared__ float  hsh[16][64];
    __shared__ float  red[16][2][2];
    __shared__ __half Tsh[64][40];

    int t = threadIdx.x;
    int lane = t & 31;

    if (blockIdx.x >= 512) {            // ---- packing part ----
        int vb = blockIdx.x - 512;
        int nw = 2048 * 8;
        int gw = vb * 8 + (t >> 5);
        const size_t total = (size_t)Bb * Nn * Nn;
        for (size_t base = (size_t)gw * 128; base < total;
             base += (size_t)nw * 128) {
            int v0 = adj[base + lane];
            int v1 = adj[base + 32 + lane];
            int v2 = adj[base + 64 + lane];
            int v3 = adj[base + 96 + lane];
            uint32_t b0 = __ballot_sync(0xffffffffu, v0 > 0);
            uint32_t b1 = __ballot_sync(0xffffffffu, v1 > 0);
            uint32_t b2 = __ballot_sync(0xffffffffu, v2 > 0);
            uint32_t b3 = __ballot_sync(0xffffffffu, v3 > 0);
            if (lane == 0)
                *(uint4*)(g_adjbits + base / 32) = make_uint4(b0, b1, b2, b3);
        }
        return;
    }

    // ---- kA part: 32 rows per block ----
    int o = t & 63, rg = t >> 6;
    int hw = (t >> 5) & 1;
    int blk = blockIdx.x;

#pragma unroll
    for (int k = 0; k < 16; k++) Wsh[t + 256 * k] = W[t + 256 * k];
    float a1 = a[o], a2 = a[64 + o];

#pragma unroll
    for (int iter = 0; iter < 2; iter++) {
        __syncthreads();
        {
            int rr = t >> 4, f4 = t & 15;
            *(float4*)&hsh[rr][f4 * 4] =
                *(const float4*)(h + (size_t)(blk * 32 + iter * 16 + rr) * 64 + f4 * 4);
        }
        __syncthreads();

        float acc[4] = {0.f, 0.f, 0.f, 0.f};
#pragma unroll
        for (int f4 = 0; f4 < 16; f4++) {
            float w0 = Wsh[(f4 * 4 + 0) * 64 + o];
            float w1 = Wsh[(f4 * 4 + 1) * 64 + o];
            float w2 = Wsh[(f4 * 4 + 2) * 64 + o];
            float w3 = Wsh[(f4 * 4 + 3) * 64 + o];
#pragma unroll
            for (int r = 0; r < 4; r++) {
                float4 hv = *(const float4*)&hsh[rg * 4 + r][f4 * 4];
                acc[r] += hv.x * w0 + hv.y * w1 + hv.z * w2 + hv.w * w3;
            }
        }
        int jloc = iter * 16 + rg * 4;
        *(half2*)&Tsh[o][jloc]     = __floats2half2_rn(acc[0], acc[1]);
        *(half2*)&Tsh[o][jloc + 2] = __floats2half2_rn(acc[2], acc[3]);

#pragma unroll
        for (int r = 0; r < 4; r++) {
            float sv = acc[r] * a1;
            float tv = acc[r] * a2;
#pragma unroll
            for (int off = 16; off; off >>= 1) {
                sv += __shfl_down_sync(0xffffffffu, sv, off);
                tv += __shfl_down_sync(0xffffffffu, tv, off);
            }
            if (lane == 0) { red[rg * 4 + r][hw][0] = sv; red[rg * 4 + r][hw][1] = tv; }
        }
        __syncthreads();
        if (t < 16) {
            int row = blk * 32 + iter * 16 + t;
            g_s[row] = red[t][0][0] + red[t][1][0];
            g_t[row] = red[t][0][1] + red[t][1][1];
        }
    }
    __syncthreads();
    {
        int f = t >> 2, c = t & 3;
        uint4 v = *(const uint4*)&Tsh[f][c * 8];
        int b  = (blk * 32) >> 11;
        int j0 = (blk * 32) & 2047;
        *(uint4*)(g_WhT + (size_t)(b * 64 + f) * Nn + j0 + c * 8) = v;
    }
}

// ---------------------------------------------------------------------------
// Kernel B: per-batch tmax
// ---------------------------------------------------------------------------
__global__ void __launch_bounds__(256) kB() {
    __shared__ float red[256];
    int b = blockIdx.x, t = threadIdx.x;
    float m = -1e30f;
#pragma unroll
    for (int k = 0; k < 8; k++) m = fmaxf(m, g_t[b * Nn + t + 256 * k]);
    red[t] = m;
    __syncthreads();
#pragma unroll
    for (int s = 128; s; s >>= 1) {
        if (t < s) red[t] = fmaxf(red[t], red[t + s]);
        __syncthreads();
    }
    if (t == 0) g_tmax[b] = red[0];
}

// ---------------------------------------------------------------------------
// Kernel D: fused masked softmax + HMMA P@Wh + ELU, bit-packed adj.
// 768 thr = 3 groups of 8 warps; 128-row i-tile; grid 128 (1 block/SM,
// 24 warps). Group g handles j-tiles {0..10 | 11..21 | 22..31} with its own
// cp.async triple buffer + named barrier. Phase-1 in f16x2; row sums via
// ones-MMA. Deposit buffer aliases group-1/2's dead Wh buffers; groups 1
// and 2 combine into group 0 sequentially.
// ---------------------------------------------------------------------------
#define PSTR     72                      // wsh row stride in halves (144B)
#define WTILE_B  (64 * PSTR * 2)         // 9216 bytes per Wh buffer
#define OFF_WSH  0                       // 3 groups x 3 buffers = 82944
#define OFF_CT   82944                   // 1024 x uint2 = 8192
#define OFF_SA   91136                   // 128 f32
#define OFF_SAP  91648                   // 128 f32
#define OFF_RS0  92160                   // 128 f32
#define OFF_RS1  92672                   // 128 f32
#define OFF_RS2  93184                   // 128 f32
#define OFF_CB   (3 * WTILE_B)           // aliases group-1/2 wsh (32KB <= 55KB)
#define SMEM_TOT 93696
#define ONE2     0x3C003C00u

__global__ void __launch_bounds__(768, 1) kD(float* __restrict__ out) {
    extern __shared__ char sm[];
    __half* wsh  = (__half*)(sm + OFF_WSH);
    uint2*  cT   = (uint2*)(sm + OFF_CT);
    float*  sAs  = (float*)(sm + OFF_SA);
    float*  sAps = (float*)(sm + OFF_SAP);
    float*  rsA[3];
    rsA[0] = (float*)(sm + OFF_RS0);
    rsA[1] = (float*)(sm + OFF_RS1);
    rsA[2] = (float*)(sm + OFF_RS2);
    float*  cbuf = (float*)(sm + OFF_CB);

    int t = threadIdx.x, lane = t & 31;
    int g = t >> 8;                      // warp-group 0/1/2 (8 warps each)
    int tl = t & 255;
    int wg = (t >> 5) & 7;
    int b = blockIdx.y, i0 = blockIdx.x * 128;

    int lr0 = wg * 16 + (lane >> 2), lr1 = lr0 + 8;
    int c2 = (lane & 3) * 2;
    const uint32_t* bits0 = g_adjbits + (size_t)(b * Nn + i0 + lr0) * 64;
    const uint32_t* bits1 = g_adjbits + (size_t)(b * Nn + i0 + lr1) * 64;
    const __half* whb = g_WhT + (size_t)b * 64 * Nn;
    uint32_t wsh_u = su32(wsh);
    int k0  = g * 11;                    // 0, 11, 22
    int cnt = (g == 2) ? 10 : 11;

#define ISSUE_WH(k) do {                                                    \
    int _buf = g * 3 + (k) % 3;                                             \
    int _f = tl >> 2, _cc = tl & 3;                                         \
    const __half* _s0 = whb + (size_t)_f * Nn + (k) * 64 + _cc * 16;        \
    uint32_t _d0 = wsh_u + _buf * WTILE_B + _f * (PSTR * 2) + _cc * 32;     \
    CP16(_d0,      _s0);                                                    \
    CP16(_d0 + 16, _s0 + 8);                                                \
    CP_COMMIT(); } while (0)

    ISSUE_WH(k0);
    ISSUE_WH(k0 + 1);

    // interleaved f16x2 exp tables: cT[j/2] = { half2(B,B+1), half2(C,C+1) }
    float tmax = g_tmax[b];
    for (int idx = t; idx < 1024; idx += 768) {
        int j = idx * 2;
        float d0 = g_t[b * Nn + j] - tmax;
        float d1 = g_t[b * Nn + j + 1] - tmax;
        float B0 = __expf(d0), B1 = __expf(d1);
        float C0 = __expf(ALPHA * d0), C1 = __expf(ALPHA * d1);
        uint32_t b2, cc2;
        CVTH2(b2, B0, B1);
        CVTH2(cc2, C0, C1);
        cT[idx] = make_uint2(b2, cc2);
    }
    if (t < 128) {
        float x = g_s[b * Nn + i0 + t] + tmax;
        float m = fmaxf(x, ALPHA * x);
        sAs[t]  = __expf(x - m);
        sAps[t] = __expf(ALPHA * x - m);
    }
    __syncthreads();

    uint32_t Ai0_2, Ap0_2, Ai1_2, Ap1_2;
    {
        float v;
        v = sAs[lr0];  CVTH2(Ai0_2, v, v);
        v = sAps[lr0]; CVTH2(Ap0_2, v, v);
        v = sAs[lr1];  CVTH2(Ai1_2, v, v);
        v = sAps[lr1]; CVTH2(Ap1_2, v, v);
    }

    int mi = lane >> 3, r8 = lane & 7;
    uint32_t b_row_off = ((mi >> 1) * 8 + r8) * (PSTR * 2) + (mi & 1) * 16;

    float d[8][4];
#pragma unroll
    for (int nb = 0; nb < 8; nb++)
#pragma unroll
        for (int q = 0; q < 4; q++) d[nb][q] = 0.f;
    float dsum[4] = {0.f, 0.f, 0.f, 0.f};

    uint2 awc0 = *(const uint2*)(bits0 + k0 * 2);
    uint2 awc1 = *(const uint2*)(bits1 + k0 * 2);
    uint2 awn0, awn1;

    for (int kk = 0; kk < cnt; kk++) {
        int k = k0 + kk;
        CP_WAIT1();
        BARG(1 + g);
        if (kk < cnt - 1) {
            awn0 = *(const uint2*)(bits0 + (k + 1) * 2);
            awn1 = *(const uint2*)(bits1 + (k + 1) * 2);
        }
        uint32_t wb = wsh_u + (g * 3 + k % 3) * WTILE_B;
#pragma unroll
        for (int kc = 0; kc < 4; kc++) {
            uint32_t wA = (kc & 2) ? awc0.y : awc0.x;
            uint32_t wB = (kc & 2) ? awc1.y : awc1.x;
            int sh = ((kc & 1) << 4) + c2;
            int idx = (k * 64 + kc * 16 + c2) >> 1;
            uint2 u0 = cT[idx];
            uint2 u1 = cT[idx + 4];

            uint32_t ia0 = (wA >> sh) & 3u;
            uint32_t ia1 = (wA >> (sh + 8)) & 3u;
            uint32_t ib0 = (wB >> sh) & 3u;
            uint32_t ib1 = (wB >> (sh + 8)) & 3u;
            uint32_t mA0 = ((ia0 & 1u) ? 0x0000FFFFu : 0u) | ((ia0 & 2u) ? 0xFFFF0000u : 0u);
            uint32_t mA1 = ((ia1 & 1u) ? 0x0000FFFFu : 0u) | ((ia1 & 2u) ? 0xFFFF0000u : 0u);
            uint32_t mB0 = ((ib0 & 1u) ? 0x0000FFFFu : 0u) | ((ib0 & 2u) ? 0xFFFF0000u : 0u);
            uint32_t mB1 = ((ib1 & 1u) ? 0x0000FFFFu : 0u) | ((ib1 & 2u) ? 0xFFFF0000u : 0u);

            uint32_t x0, x1, fa0, fa1, fa2, fa3;
            HMUL2(x0, Ai0_2, u0.x); HMUL2(x1, Ap0_2, u0.y); HMAX2(fa0, x0, x1);
            HMUL2(x0, Ai1_2, u0.x); HMUL2(x1, Ap1_2, u0.y); HMAX2(fa1, x0, x1);
            HMUL2(x0, Ai0_2, u1.x); HMUL2(x1, Ap0_2, u1.y); HMAX2(fa2, x0, x1);
            HMUL2(x0, Ai1_2, u1.x); HMUL2(x1, Ap1_2, u1.y); HMAX2(fa3, x0, x1);
            fa0 &= mA0; fa1 &= mB0; fa2 &= mA1; fa3 &= mB1;

            MMA16816(dsum, fa0, fa1, fa2, fa3, ONE2, ONE2);
#pragma unroll
            for (int nbp = 0; nbp < 4; nbp++) {
                uint32_t q0, q1, q2, q3;
                LDSM4(q0, q1, q2, q3,
                      wb + nbp * 16 * (PSTR * 2) + b_row_off + kc * 32);
                MMA16816(d[nbp * 2],     fa0, fa1, fa2, fa3, q0, q1);
                MMA16816(d[nbp * 2 + 1], fa0, fa1, fa2, fa3, q2, q3);
            }
        }
        awc0 = awn0; awc1 = awn1;
        if (kk < cnt - 2) ISSUE_WH(k + 2);
        else CP_COMMIT();
    }

    // row sums from the ones-MMA
    if ((lane & 3) == 0) {
        rsA[g][lr0] = dsum[0];
        rsA[g][lr1] = dsum[2];
    }
    __syncthreads();                     // all pipelines done; wsh dead

    // combine group 1 into group 0
    if (g == 1) {
#pragma unroll
        for (int nb = 0; nb < 8; nb++)
#pragma unroll
            for (int q = 0; q < 4; q++)
                cbuf[(nb * 4 + q) * 256 + tl] = d[nb][q];
    }
    __syncthreads();
    if (g == 0) {
#pragma unroll
        for (int nb = 0; nb < 8; nb++)
#pragma unroll
            for (int q = 0; q < 4; q++)
                d[nb][q] += cbuf[(nb * 4 + q) * 256 + tl];
    }
    __syncthreads();
    // combine group 2 into group 0
    if (g == 2) {
#pragma unroll
        for (int nb = 0; nb < 8; nb++)
#pragma unroll
            for (int q = 0; q < 4; q++)
                cbuf[(nb * 4 + q) * 256 + tl] = d[nb][q];
    }
    __syncthreads();

    if (g == 0) {
        float* rs0 = rsA[0];
        float* rs1 = rsA[1];
        float* rs2 = rsA[2];
        float l0 = 1.0f / (rs0[lr0] + rs1[lr0] + rs2[lr0]);
        float l1 = 1.0f / (rs0[lr1] + rs1[lr1] + rs2[lr1]);
        float* o0 = out + (size_t)(b * Nn + i0 + lr0) * 64 + c2;
        float* o1 = out + (size_t)(b * Nn + i0 + lr1) * 64 + c2;
#pragma unroll
        for (int nb = 0; nb < 8; nb++) {
            float x0 = (d[nb][0] + cbuf[(nb * 4 + 0) * 256 + tl]) * l0;
            float x1 = (d[nb][1] + cbuf[(nb * 4 + 1) * 256 + tl]) * l0;
            float y0 = (d[nb][2] + cbuf[(nb * 4 + 2) * 256 + tl]) * l1;
            float y1 = (d[nb][3] + cbuf[(nb * 4 + 3) * 256 + tl]) * l1;
            float2 v0, v1;
            v0.x = x0 > 0.f ? x0 : expm1f(x0);
            v0.y = x1 > 0.f ? x1 : expm1f(x1);
            v1.x = y0 > 0.f ? y0 : expm1f(y0);
            v1.y = y1 > 0.f ? y1 : expm1f(y1);
            *(float2*)(o0 + nb * 8) = v0;
            *(float2*)(o1 + nb * 8) = v1;
        }
    }
}

// ---------------------------------------------------------------------------
extern "C" void kernel_launch(void* const* d_in, const int* in_sizes, int n_in,
                              void* d_out, int out_size) {
    const float* h   = (const float*)d_in[0];   // (8,2048,64) f32
    const int*   adj = (const int*)d_in[1];     // (8,2048,2048) i32
    const float* W   = (const float*)d_in[2];   // (64,64) f32
    const float* a   = (const float*)d_in[3];   // (128,1) f32
    float* out = (float*)d_out;                 // (8,2048,64) f32

    cudaFuncSetAttribute(kD, cudaFuncAttributeMaxDynamicSharedMemorySize, SMEM_TOT);

    kPA<<<2560, 256>>>(h, W, a, adj);
    kB<<<Bb, 256>>>();
    kD<<<dim3(Nn / 128, Bb), 768, SMEM_TOT>>>(out);
}

// round 15
// speedup vs baseline: 1.1674x; 1.0602x over previous
#include <cuda_runtime.h>
#include <cuda_fp16.h>
#include <cstdint>

#define Bb 8
#define Nn 2048
#define ALPHA 0.2f

// ---------------- device globals (no allocation allowed) -------------------
__device__ float    g_s[Bb * Nn];
__device__ float    g_t[Bb * Nn];
__device__ float    g_tmax[Bb];
__device__ __half   g_WhT[Bb * 64 * Nn];       // [b][f][j], fp16, 2MB
__device__ uint32_t g_adjbits[Bb * Nn * 64];   // adj bit-packed, 4MB

// ---------------- PTX helpers ----------------------------------------------
__device__ __forceinline__ uint32_t su32(const void* p) {
    uint32_t a;
    asm("{ .reg .u64 t; cvta.to.shared.u64 t, %1; cvt.u32.u64 %0, t; }"
        : "=r"(a) : "l"(p));
    return a;
}
#define CVTH2(r, lo, hi) \
    asm("cvt.rn.f16x2.f32 %0, %2, %1;" : "=r"(r) : "f"(lo), "f"(hi))
#define HMUL2(r, a, b) \
    asm("mul.f16x2 %0, %1, %2;" : "=r"(r) : "r"(a), "r"(b))
#define HMAX2(r, a, b) \
    asm("max.f16x2 %0, %1, %2;" : "=r"(r) : "r"(a), "r"(b))

#define LDSM4(r0, r1, r2, r3, addr) \
    asm volatile("ldmatrix.sync.aligned.m8n8.x4.shared.b16 {%0,%1,%2,%3}, [%4];" \
                 : "=r"(r0), "=r"(r1), "=r"(r2), "=r"(r3) : "r"(addr))

#define MMA16816(dd, a0, a1, a2, a3, b0, b1) \
    asm volatile("mma.sync.aligned.m16n8k16.row.col.f32.f16.f16.f32 " \
                 "{%0,%1,%2,%3}, {%4,%5,%6,%7}, {%8,%9}, {%0,%1,%2,%3};" \
                 : "+f"((dd)[0]), "+f"((dd)[1]), "+f"((dd)[2]), "+f"((dd)[3]) \
                 : "r"(a0), "r"(a1), "r"(a2), "r"(a3), "r"(b0), "r"(b1))

#define CP16(dst, src) \
    asm volatile("cp.async.cg.shared.global [%0], [%1], 16;" \
                 :: "r"(dst), "l"(src) : "memory")
#define CP_COMMIT() asm volatile("cp.async.commit_group;" ::: "memory")
#define CP_WAIT1()  asm volatile("cp.async.wait_group 1;" ::: "memory")
#define BARG(id) \
    asm volatile("bar.sync %0, 128;" :: "r"(id) : "memory")

// ---------------------------------------------------------------------------
// Kernel PA: blocks 0..511 do Wh=h@W (32 rows each) + s,t + WhT emit;
// blocks 512..2559 bit-pack adj via warp ballots (2x unrolled, MLP=8).
// ---------------------------------------------------------------------------
__global__ void __launch_bounds__(256) kPA(const float* __restrict__ h,
                                           const float* __restrict__ W,
                                           const float* __restrict__ a,
                                           const int* __restrict__ adj) {
    __shared__ float  Wsh[64 * 64];
    __shared__ float  hsh[16][64];
    __shared__ float  red[16][2][2];
    __shared__ __half Tsh[64][40];

    int t = threadIdx.x;
    int lane = t & 31;

    if (blockIdx.x >= 512) {            // ---- packing part ----
        int vb = blockIdx.x - 512;
        int nw = 2048 * 8;
        int gw = vb * 8 + (t >> 5);
        const size_t total = (size_t)Bb * Nn * Nn;
        for (size_t base = (size_t)gw * 256; base < total;
             base += (size_t)nw * 256) {
            int v0 = adj[base + lane];
            int v1 = adj[base + 32 + lane];
            int v2 = adj[base + 64 + lane];
            int v3 = adj[base + 96 + lane];
            int v4 = adj[base + 128 + lane];
            int v5 = adj[base + 160 + lane];
            int v6 = adj[base + 192 + lane];
            int v7 = adj[base + 224 + lane];
            uint32_t b0 = __ballot_sync(0xffffffffu, v0 > 0);
            uint32_t b1 = __ballot_sync(0xffffffffu, v1 > 0);
            uint32_t b2 = __ballot_sync(0xffffffffu, v2 > 0);
            uint32_t b3 = __ballot_sync(0xffffffffu, v3 > 0);
            uint32_t b4 = __ballot_sync(0xffffffffu, v4 > 0);
            uint32_t b5 = __ballot_sync(0xffffffffu, v5 > 0);
            uint32_t b6 = __ballot_sync(0xffffffffu, v6 > 0);
            uint32_t b7 = __ballot_sync(0xffffffffu, v7 > 0);
            if (lane == 0) {
                *(uint4*)(g_adjbits + base / 32)     = make_uint4(b0, b1, b2, b3);
                *(uint4*)(g_adjbits + base / 32 + 4) = make_uint4(b4, b5, b6, b7);
            }
        }
        return;
    }

    // ---- kA part: 32 rows per block ----
    int o = t & 63, rg = t >> 6;
    int hw = (t >> 5) & 1;
    int blk = blockIdx.x;

#pragma unroll
    for (int k = 0; k < 16; k++) Wsh[t + 256 * k] = W[t + 256 * k];
    float a1 = a[o], a2 = a[64 + o];

#pragma unroll
    for (int iter = 0; iter < 2; iter++) {
        __syncthreads();
        {
            int rr = t >> 4, f4 = t & 15;
            *(float4*)&hsh[rr][f4 * 4] =
                *(const float4*)(h + (size_t)(blk * 32 + iter * 16 + rr) * 64 + f4 * 4);
        }
        __syncthreads();

        float acc[4] = {0.f, 0.f, 0.f, 0.f};
#pragma unroll
        for (int f4 = 0; f4 < 16; f4++) {
            float w0 = Wsh[(f4 * 4 + 0) * 64 + o];
            float w1 = Wsh[(f4 * 4 + 1) * 64 + o];
            float w2 = Wsh[(f4 * 4 + 2) * 64 + o];
            float w3 = Wsh[(f4 * 4 + 3) * 64 + o];
#pragma unroll
            for (int r = 0; r < 4; r++) {
                float4 hv = *(const float4*)&hsh[rg * 4 + r][f4 * 4];
                acc[r] += hv.x * w0 + hv.y * w1 + hv.z * w2 + hv.w * w3;
            }
        }
        int jloc = iter * 16 + rg * 4;
        *(half2*)&Tsh[o][jloc]     = __floats2half2_rn(acc[0], acc[1]);
        *(half2*)&Tsh[o][jloc + 2] = __floats2half2_rn(acc[2], acc[3]);

#pragma unroll
        for (int r = 0; r < 4; r++) {
            float sv = acc[r] * a1;
            float tv = acc[r] * a2;
#pragma unroll
            for (int off = 16; off; off >>= 1) {
                sv += __shfl_down_sync(0xffffffffu, sv, off);
                tv += __shfl_down_sync(0xffffffffu, tv, off);
            }
            if (lane == 0) { red[rg * 4 + r][hw][0] = sv; red[rg * 4 + r][hw][1] = tv; }
        }
        __syncthreads();
        if (t < 16) {
            int row = blk * 32 + iter * 16 + t;
            g_s[row] = red[t][0][0] + red[t][1][0];
            g_t[row] = red[t][0][1] + red[t][1][1];
        }
    }
    __syncthreads();
    {
        int f = t >> 2, c = t & 3;
        uint4 v = *(const uint4*)&Tsh[f][c * 8];
        int b  = (blk * 32) >> 11;
        int j0 = (blk * 32) & 2047;
        *(uint4*)(g_WhT + (size_t)(b * 64 + f) * Nn + j0 + c * 8) = v;
    }
}

// ---------------------------------------------------------------------------
// Kernel B: per-batch tmax
// ---------------------------------------------------------------------------
__global__ void __launch_bounds__(256) kB() {
    __shared__ float red[256];
    int b = blockIdx.x, t = threadIdx.x;
    float m = -1e30f;
#pragma unroll
    for (int k = 0; k < 8; k++) m = fmaxf(m, g_t[b * Nn + t + 256 * k]);
    red[t] = m;
    __syncthreads();
#pragma unroll
    for (int s = 128; s; s >>= 1) {
        if (t < s) red[t] = fmaxf(red[t], red[t + s]);
        __syncthreads();
    }
    if (t == 0) g_tmax[b] = red[0];
}

// ---------------------------------------------------------------------------
// Kernel D: fused masked softmax + HMMA P@Wh + ELU, bit-packed adj.
// 512 thr = 4 groups x 4 warps; 128-row i-tile; grid 128. Group g handles
// j-tiles [g*8, g*8+8) with its own cp.async triple buffer + named barrier.
// EACH WARP OWNS 32 ROWS (two A-fragment row-sets) so every LDSM'd
// B-fragment feeds 4 MMAs instead of 2 -> LDSM + cT smem traffic halves.
// Phase-1 f16x2; row sums via ones-MMA; deposit buffer aliases dead wsh.
// ---------------------------------------------------------------------------
#define PSTR     72                      // wsh row stride in halves (144B)
#define WTILE_B  (64 * PSTR * 2)         // 9216 bytes per Wh buffer
#define OFF_WSH  0                       // 4 groups x 3 buffers = 110592
#define OFF_CT   110592                  // 1024 x uint2 = 8192
#define OFF_SA   118784                  // 128 f32
#define OFF_SAP  119296                  // 128 f32
#define OFF_RS   119808                  // 4 x 128 f32 = 2048
#define OFF_CB   (3 * WTILE_B)           // aliases group-1/2 wsh (32KB)
#define SMEM_TOT 121856
#define ONE2     0x3C003C00u

__global__ void __launch_bounds__(512, 1) kD(float* __restrict__ out) {
    extern __shared__ char sm[];
    __half* wsh  = (__half*)(sm + OFF_WSH);
    uint2*  cT   = (uint2*)(sm + OFF_CT);
    float*  sAs  = (float*)(sm + OFF_SA);
    float*  sAps = (float*)(sm + OFF_SAP);
    float*  rs   = (float*)(sm + OFF_RS);
    float*  cbuf = (float*)(sm + OFF_CB);

    int t = threadIdx.x, lane = t & 31;
    int g = t >> 7;                      // warp-group 0..3 (4 warps each)
    int tl = t & 127;
    int w = (t >> 5) & 3;                // warp within group
    int b = blockIdx.y, i0 = blockIdx.x * 128;

    int c2 = (lane & 3) * 2;
    int rbase = w * 32 + (lane >> 2);    // stream q = r*2+s -> row rbase+r*16+s*8
    const __half* whb = g_WhT + (size_t)b * 64 * Nn;
    uint32_t wsh_u = su32(wsh);
    int k0 = g * 8;

    const uint32_t* bitsp[4];
#pragma unroll
    for (int q = 0; q < 4; q++)
        bitsp[q] = g_adjbits +
            (size_t)(b * Nn + i0 + rbase + (q >> 1) * 16 + (q & 1) * 8) * 64;

#define ISSUE_WH(k) do {                                                    \
    int _buf = g * 3 + (k) % 3;                                             \
    int _f = tl >> 1, _hf = tl & 1;                                         \
    const __half* _s0 = whb + (size_t)_f * Nn + (k) * 64 + _hf * 32;        \
    uint32_t _d0 = wsh_u + _buf * WTILE_B + _f * (PSTR * 2) + _hf * 64;     \
    CP16(_d0,      _s0);                                                    \
    CP16(_d0 + 16, _s0 + 8);                                                \
    CP16(_d0 + 32, _s0 + 16);                                               \
    CP16(_d0 + 48, _s0 + 24);                                               \
    CP_COMMIT(); } while (0)

    ISSUE_WH(k0);
    ISSUE_WH(k0 + 1);

    // interleaved f16x2 exp tables
    float tmax = g_tmax[b];
#pragma unroll
    for (int q = 0; q < 2; q++) {
        int idx = t + 512 * q;           // 0..1023
        int j = idx * 2;
        float d0 = g_t[b * Nn + j] - tmax;
        float d1 = g_t[b * Nn + j + 1] - tmax;
        float B0 = __expf(d0), B1 = __expf(d1);
        float C0 = __expf(ALPHA * d0), C1 = __expf(ALPHA * d1);
        uint32_t b2, cc2;
        CVTH2(b2, B0, B1);
        CVTH2(cc2, C0, C1);
        cT[idx] = make_uint2(b2, cc2);
    }
    if (t < 128) {
        float x = g_s[b * Nn + i0 + t] + tmax;
        float m = fmaxf(x, ALPHA * x);
        sAs[t]  = __expf(x - m);
        sAps[t] = __expf(ALPHA * x - m);
    }
    __syncthreads();

    uint32_t Aih[4], Aph[4];
#pragma unroll
    for (int q = 0; q < 4; q++) {
        int row = rbase + (q >> 1) * 16 + (q & 1) * 8;
        float v = sAs[row];  CVTH2(Aih[q], v, v);
        v = sAps[row];       CVTH2(Aph[q], v, v);
    }

    int mi = lane >> 3, r8 = lane & 7;
    uint32_t b_row_off = ((mi >> 1) * 8 + r8) * (PSTR * 2) + (mi & 1) * 16;

    float d[2][8][4];
#pragma unroll
    for (int r = 0; r < 2; r++)
#pragma unroll
        for (int nb = 0; nb < 8; nb++)
#pragma unroll
            for (int q = 0; q < 4; q++) d[r][nb][q] = 0.f;
    float dsum[2][4] = {{0.f, 0.f, 0.f, 0.f}, {0.f, 0.f, 0.f, 0.f}};

    uint2 awc[4], awn[4];
#pragma unroll
    for (int q = 0; q < 4; q++) awc[q] = *(const uint2*)(bitsp[q] + k0 * 2);

    for (int kk = 0; kk < 8; kk++) {
        int k = k0 + kk;
        CP_WAIT1();
        BARG(1 + g);
        if (kk < 7) {
#pragma unroll
            for (int q = 0; q < 4; q++)
                awn[q] = *(const uint2*)(bitsp[q] + (k + 1) * 2);
        }
        uint32_t wb = wsh_u + (g * 3 + k % 3) * WTILE_B;
#pragma unroll
        for (int kc = 0; kc < 4; kc++) {
            int idx = k * 32 + kc * 8 + (lane & 3);
            uint2 u0 = cT[idx];
            uint2 u1 = cT[idx + 4];
            int sh = ((kc & 1) << 4) + c2;

            uint32_t fa[2][4];
#pragma unroll
            for (int r = 0; r < 2; r++) {
                uint32_t wA = (kc & 2) ? awc[r * 2].y     : awc[r * 2].x;
                uint32_t wB = (kc & 2) ? awc[r * 2 + 1].y : awc[r * 2 + 1].x;
                uint32_t ia0 = (wA >> sh) & 3u;
                uint32_t ia1 = (wA >> (sh + 8)) & 3u;
                uint32_t ib0 = (wB >> sh) & 3u;
                uint32_t ib1 = (wB >> (sh + 8)) & 3u;
                uint32_t mA0 = ((ia0 & 1u) ? 0x0000FFFFu : 0u) | ((ia0 & 2u) ? 0xFFFF0000u : 0u);
                uint32_t mA1 = ((ia1 & 1u) ? 0x0000FFFFu : 0u) | ((ia1 & 2u) ? 0xFFFF0000u : 0u);
                uint32_t mB0 = ((ib0 & 1u) ? 0x0000FFFFu : 0u) | ((ib0 & 2u) ? 0xFFFF0000u : 0u);
                uint32_t mB1 = ((ib1 & 1u) ? 0x0000FFFFu : 0u) | ((ib1 & 2u) ? 0xFFFF0000u : 0u);

                uint32_t x0, x1;
                HMUL2(x0, Aih[r * 2], u0.x);     HMUL2(x1, Aph[r * 2], u0.y);
                HMAX2(fa[r][0], x0, x1);
                HMUL2(x0, Aih[r * 2 + 1], u0.x); HMUL2(x1, Aph[r * 2 + 1], u0.y);
                HMAX2(fa[r][1], x0, x1);
                HMUL2(x0, Aih[r * 2], u1.x);     HMUL2(x1, Aph[r * 2], u1.y);
                HMAX2(fa[r][2], x0, x1);
                HMUL2(x0, Aih[r * 2 + 1], u1.x); HMUL2(x1, Aph[r * 2 + 1], u1.y);
                HMAX2(fa[r][3], x0, x1);
                fa[r][0] &= mA0; fa[r][1] &= mB0; fa[r][2] &= mA1; fa[r][3] &= mB1;

                MMA16816(dsum[r], fa[r][0], fa[r][1], fa[r][2], fa[r][3], ONE2, ONE2);
            }
#pragma unroll
            for (int nbp = 0; nbp < 4; nbp++) {
                uint32_t q0, q1, q2, q3;
                LDSM4(q0, q1, q2, q3,
                      wb + nbp * 16 * (PSTR * 2) + b_row_off + kc * 32);
                MMA16816(d[0][nbp * 2],     fa[0][0], fa[0][1], fa[0][2], fa[0][3], q0, q1);
                MMA16816(d[0][nbp * 2 + 1], fa[0][0], fa[0][1], fa[0][2], fa[0][3], q2, q3);
                MMA16816(d[1][nbp * 2],     fa[1][0], fa[1][1], fa[1][2], fa[1][3], q0, q1);
                MMA16816(d[1][nbp * 2 + 1], fa[1][0], fa[1][1], fa[1][2], fa[1][3], q2, q3);
            }
        }
#pragma unroll
        for (int q = 0; q < 4; q++) awc[q] = awn[q];
        if (kk < 6) ISSUE_WH(k + 2);
        else CP_COMMIT();
    }

    // row sums from ones-MMA: dsum[r][0] -> row rbase+r*16, dsum[r][2] -> +8
    if ((lane & 3) == 0) {
#pragma unroll
        for (int r = 0; r < 2; r++) {
            rs[g * 128 + rbase + r * 16]     = dsum[r][0];
            rs[g * 128 + rbase + r * 16 + 8] = dsum[r][2];
        }
    }
    __syncthreads();                     // pipelines done; wsh dead -> alias OK

    // sequential combine of groups 1..3 into group 0
#pragma unroll
    for (int gp = 1; gp < 4; gp++) {
        if (g == gp) {
#pragma unroll
            for (int r = 0; r < 2; r++)
#pragma unroll
                for (int nb = 0; nb < 8; nb++)
#pragma unroll
                    for (int q = 0; q < 4; q++)
                        cbuf[((r * 8 + nb) * 4 + q) * 128 + tl] = d[r][nb][q];
        }
        __syncthreads();
        if (g == 0) {
#pragma unroll
            for (int r = 0; r < 2; r++)
#pragma unroll
                for (int nb = 0; nb < 8; nb++)
#pragma unroll
                    for (int q = 0; q < 4; q++)
                        d[r][nb][q] += cbuf[((r * 8 + nb) * 4 + q) * 128 + tl];
        }
        __syncthreads();
    }

    if (g == 0) {
#pragma unroll
        for (int r = 0; r < 2; r++) {
            int row0 = rbase + r * 16, row1 = row0 + 8;
            float l0 = 1.0f / (rs[row0] + rs[128 + row0] + rs[256 + row0] + rs[384 + row0]);
            float l1 = 1.0f / (rs[row1] + rs[128 + row1] + rs[256 + row1] + rs[384 + row1]);
            float* o0 = out + (size_t)(b * Nn + i0 + row0) * 64 + c2;
            float* o1 = out + (size_t)(b * Nn + i0 + row1) * 64 + c2;
#pragma unroll
            for (int nb = 0; nb < 8; nb++) {
                float x0 = d[r][nb][0] * l0, x1 = d[r][nb][1] * l0;
                float y0 = d[r][nb][2] * l1, y1 = d[r][nb][3] * l1;
                float2 v0, v1;
                v0.x = x0 > 0.f ? x0 : expm1f(x0);
                v0.y = x1 > 0.f ? x1 : expm1f(x1);
                v1.x = y0 > 0.f ? y0 : expm1f(y0);
                v1.y = y1 > 0.f ? y1 : expm1f(y1);
                *(float2*)(o0 + nb * 8) = v0;
                *(float2*)(o1 + nb * 8) = v1;
            }
        }
    }
}

// ---------------------------------------------------------------------------
extern "C" void kernel_launch(void* const* d_in, const int* in_sizes, int n_in,
                              void* d_out, int out_size) {
    const float* h   = (const float*)d_in[0];   // (8,2048,64) f32
    const int*   adj = (const int*)d_in[1];     // (8,2048,2048) i32
    const float* W   = (const float*)d_in[2];   // (64,64) f32
    const float* a   = (const float*)d_in[3];   // (128,1) f32
    float* out = (float*)d_out;                 // (8,2048,64) f32

    cudaFuncSetAttribute(kD, cudaFuncAttributeMaxDynamicSharedMemorySize, SMEM_TOT);

    kPA<<<2560, 256>>>(h, W, a, adj);
    kB<<<Bb, 256>>>();
    kD<<<dim3(Nn / 128, Bb), 512, SMEM_TOT>>>(out);
}

// round 16
// speedup vs baseline: 1.2522x; 1.0726x over previous
#include <cuda_runtime.h>
#include <cuda_fp16.h>
#include <cstdint>

#define Bb 8
#define Nn 2048
#define ALPHA 0.2f

// ---------------- device globals (no allocation allowed) -------------------
__device__ float    g_s[Bb * Nn];
__device__ float    g_t[Bb * Nn];
__device__ float    g_tmax[Bb];
__device__ __half   g_WhT[Bb * 64 * Nn];       // [b][f][j], fp16, 2MB
__device__ uint32_t g_adjbits[Bb * Nn * 64];   // adj bit-packed, 4MB

// ---------------- PTX helpers ----------------------------------------------
__device__ __forceinline__ uint32_t su32(const void* p) {
    uint32_t a;
    asm("{ .reg .u64 t; cvta.to.shared.u64 t, %1; cvt.u32.u64 %0, t; }"
        : "=r"(a) : "l"(p));
    return a;
}
#define CVTH2(r, lo, hi) \
    asm("cvt.rn.f16x2.f32 %0, %2, %1;" : "=r"(r) : "f"(lo), "f"(hi))
#define HMUL2(r, a, b) \
    asm("mul.f16x2 %0, %1, %2;" : "=r"(r) : "r"(a), "r"(b))
#define HMAX2(r, a, b) \
    asm("max.f16x2 %0, %1, %2;" : "=r"(r) : "r"(a), "r"(b))

#define LDSM4(r0, r1, r2, r3, addr) \
    asm volatile("ldmatrix.sync.aligned.m8n8.x4.shared.b16 {%0,%1,%2,%3}, [%4];" \
                 : "=r"(r0), "=r"(r1), "=r"(r2), "=r"(r3) : "r"(addr))

#define MMA16816(dd, a0, a1, a2, a3, b0, b1) \
    asm volatile("mma.sync.aligned.m16n8k16.row.col.f32.f16.f16.f32 " \
                 "{%0,%1,%2,%3}, {%4,%5,%6,%7}, {%8,%9}, {%0,%1,%2,%3};" \
                 : "+f"((dd)[0]), "+f"((dd)[1]), "+f"((dd)[2]), "+f"((dd)[3]) \
                 : "r"(a0), "r"(a1), "r"(a2), "r"(a3), "r"(b0), "r"(b1))

#define CP16(dst, src) \
    asm volatile("cp.async.cg.shared.global [%0], [%1], 16;" \
                 :: "r"(dst), "l"(src) : "memory")
#define CP_COMMIT() asm volatile("cp.async.commit_group;" ::: "memory")
#define CP_WAIT1()  asm volatile("cp.async.wait_group 1;" ::: "memory")
#define BARG(id) \
    asm volatile("bar.sync %0, 256;" :: "r"(id) : "memory")

// ---------------------------------------------------------------------------
// Kernel PA: blocks 0..511 do Wh=h@W (32 rows each) + s,t + WhT emit;
// blocks 512..2559 bit-pack adj via warp ballots (4x unrolled, MLP=16).
// ---------------------------------------------------------------------------
__global__ void __launch_bounds__(256) kPA(const float* __restrict__ h,
                                           const float* __restrict__ W,
                                           const float* __restrict__ a,
                                           const int* __restrict__ adj) {
    __shared__ float  Wsh[64 * 64];
    __shared__ float  hsh[16][64];
    __shared__ float  red[16][2][2];
    __shared__ __half Tsh[64][40];

    int t = threadIdx.x;
    int lane = t & 31;

    if (blockIdx.x >= 512) {            // ---- packing part ----
        int vb = blockIdx.x - 512;
        int nw = 2048 * 8;
        int gw = vb * 8 + (t >> 5);
        const size_t total = (size_t)Bb * Nn * Nn;
        for (size_t base = (size_t)gw * 512; base < total;
             base += (size_t)nw * 512) {
            int v[16];
#pragma unroll
            for (int q = 0; q < 16; q++)
                v[q] = adj[base + q * 32 + lane];
            uint32_t bl[16];
#pragma unroll
            for (int q = 0; q < 16; q++)
                bl[q] = __ballot_sync(0xffffffffu, v[q] > 0);
            if (lane == 0) {
#pragma unroll
                for (int q = 0; q < 4; q++)
                    *(uint4*)(g_adjbits + base / 32 + q * 4) =
                        make_uint4(bl[q * 4], bl[q * 4 + 1],
                                   bl[q * 4 + 2], bl[q * 4 + 3]);
            }
        }
        return;
    }

    // ---- kA part: 32 rows per block ----
    int o = t & 63, rg = t >> 6;
    int hw = (t >> 5) & 1;
    int blk = blockIdx.x;

#pragma unroll
    for (int k = 0; k < 16; k++) Wsh[t + 256 * k] = W[t + 256 * k];
    float a1 = a[o], a2 = a[64 + o];

#pragma unroll
    for (int iter = 0; iter < 2; iter++) {
        __syncthreads();
        {
            int rr = t >> 4, f4 = t & 15;
            *(float4*)&hsh[rr][f4 * 4] =
                *(const float4*)(h + (size_t)(blk * 32 + iter * 16 + rr) * 64 + f4 * 4);
        }
        __syncthreads();

        float acc[4] = {0.f, 0.f, 0.f, 0.f};
#pragma unroll
        for (int f4 = 0; f4 < 16; f4++) {
            float w0 = Wsh[(f4 * 4 + 0) * 64 + o];
            float w1 = Wsh[(f4 * 4 + 1) * 64 + o];
            float w2 = Wsh[(f4 * 4 + 2) * 64 + o];
            float w3 = Wsh[(f4 * 4 + 3) * 64 + o];
#pragma unroll
            for (int r = 0; r < 4; r++) {
                float4 hv = *(const float4*)&hsh[rg * 4 + r][f4 * 4];
                acc[r] += hv.x * w0 + hv.y * w1 + hv.z * w2 + hv.w * w3;
            }
        }
        int jloc = iter * 16 + rg * 4;
        *(half2*)&Tsh[o][jloc]     = __floats2half2_rn(acc[0], acc[1]);
        *(half2*)&Tsh[o][jloc + 2] = __floats2half2_rn(acc[2], acc[3]);

#pragma unroll
        for (int r = 0; r < 4; r++) {
            float sv = acc[r] * a1;
            float tv = acc[r] * a2;
#pragma unroll
            for (int off = 16; off; off >>= 1) {
                sv += __shfl_down_sync(0xffffffffu, sv, off);
                tv += __shfl_down_sync(0xffffffffu, tv, off);
            }
            if (lane == 0) { red[rg * 4 + r][hw][0] = sv; red[rg * 4 + r][hw][1] = tv; }
        }
        __syncthreads();
        if (t < 16) {
            int row = blk * 32 + iter * 16 + t;
            g_s[row] = red[t][0][0] + red[t][1][0];
            g_t[row] = red[t][0][1] + red[t][1][1];
        }
    }
    __syncthreads();
    {
        int f = t >> 2, c = t & 3;
        uint4 v = *(const uint4*)&Tsh[f][c * 8];
        int b  = (blk * 32) >> 11;
        int j0 = (blk * 32) & 2047;
        *(uint4*)(g_WhT + (size_t)(b * 64 + f) * Nn + j0 + c * 8) = v;
    }
}

// ---------------------------------------------------------------------------
// Kernel B: per-batch tmax
// ---------------------------------------------------------------------------
__global__ void __launch_bounds__(256) kB() {
    __shared__ float red[256];
    int b = blockIdx.x, t = threadIdx.x;
    float m = -1e30f;
#pragma unroll
    for (int k = 0; k < 8; k++) m = fmaxf(m, g_t[b * Nn + t + 256 * k]);
    red[t] = m;
    __syncthreads();
#pragma unroll
    for (int s = 128; s; s >>= 1) {
        if (t < s) red[t] = fmaxf(red[t], red[t + s]);
        __syncthreads();
    }
    if (t == 0) g_tmax[b] = red[0];
}

// ---------------------------------------------------------------------------
// Kernel D (R12 exact): fused masked softmax + HMMA P@Wh + ELU.
// 512 thr = 2 groups of 8 warps; group g handles j-tiles [g*16, g*16+16)
// with its own cp.async triple buffer + named barrier. Phase-1 f16x2;
// row sums via ones-MMA.
// ---------------------------------------------------------------------------
#define PSTR     72                      // wsh row stride in halves (144B)
#define WTILE_B  (64 * PSTR * 2)         // 9216 bytes per Wh buffer
#define OFF_WSH  0                       // 2 groups x 3 buffers = 55296
#define OFF_CT   55296                   // 1024 x uint2 = 8192
#define OFF_SA   63488                   // 128 f32
#define OFF_SAP  64000                   // 128 f32
#define OFF_RS0  64512                   // 128 f32
#define OFF_RS1  65024                   // 128 f32
#define OFF_CB   65536                   // 8192 f32 (group-1 d frags, 32KB)
#define SMEM_TOT 98304
#define ONE2     0x3C003C00u

__global__ void __launch_bounds__(512) kD(float* __restrict__ out) {
    extern __shared__ char sm[];
    __half* wsh  = (__half*)(sm + OFF_WSH);
    uint2*  cT   = (uint2*)(sm + OFF_CT);
    float*  sAs  = (float*)(sm + OFF_SA);
    float*  sAps = (float*)(sm + OFF_SAP);
    float*  rs0  = (float*)(sm + OFF_RS0);
    float*  rs1  = (float*)(sm + OFF_RS1);
    float*  cbuf = (float*)(sm + OFF_CB);

    int t = threadIdx.x, lane = t & 31;
    int g = t >> 8;                      // warp-group 0/1
    int tl = t & 255;
    int wg = (t >> 5) & 7;
    int b = blockIdx.y, i0 = blockIdx.x * 128;

    int lr0 = wg * 16 + (lane >> 2), lr1 = lr0 + 8;
    int c2 = (lane & 3) * 2;
    const uint32_t* bits0 = g_adjbits + (size_t)(b * Nn + i0 + lr0) * 64;
    const uint32_t* bits1 = g_adjbits + (size_t)(b * Nn + i0 + lr1) * 64;
    const __half* whb = g_WhT + (size_t)b * 64 * Nn;
    uint32_t wsh_u = su32(wsh);
    int k0 = g * 16;

#define ISSUE_WH(k) do {                                                    \
    int _buf = g * 3 + (k) % 3;                                             \
    int _f = tl >> 2, _cc = tl & 3;                                         \
    const __half* _s0 = whb + (size_t)_f * Nn + (k) * 64 + _cc * 16;        \
    uint32_t _d0 = wsh_u + _buf * WTILE_B + _f * (PSTR * 2) + _cc * 32;     \
    CP16(_d0,      _s0);                                                    \
    CP16(_d0 + 16, _s0 + 8);                                                \
    CP_COMMIT(); } while (0)

    ISSUE_WH(k0);
    ISSUE_WH(k0 + 1);

    // interleaved f16x2 exp tables: cT[j/2] = { half2(B,B+1), half2(C,C+1) }
    float tmax = g_tmax[b];
#pragma unroll
    for (int q = 0; q < 2; q++) {
        int idx = t + 512 * q;           // 0..1023
        int j = idx * 2;
        float d0 = g_t[b * Nn + j] - tmax;
        float d1 = g_t[b * Nn + j + 1] - tmax;
        float B0 = __expf(d0), B1 = __expf(d1);
        float C0 = __expf(ALPHA * d0), C1 = __expf(ALPHA * d1);
        uint32_t b2, cc2;
        CVTH2(b2, B0, B1);
        CVTH2(cc2, C0, C1);
        cT[idx] = make_uint2(b2, cc2);
    }
    if (t < 128) {
        float x = g_s[b * Nn + i0 + t] + tmax;
        float m = fmaxf(x, ALPHA * x);
        sAs[t]  = __expf(x - m);
        sAps[t] = __expf(ALPHA * x - m);
    }
    __syncthreads();

    uint32_t Ai0_2, Ap0_2, Ai1_2, Ap1_2;
    {
        float v;
        v = sAs[lr0];  CVTH2(Ai0_2, v, v);
        v = sAps[lr0]; CVTH2(Ap0_2, v, v);
        v = sAs[lr1];  CVTH2(Ai1_2, v, v);
        v = sAps[lr1]; CVTH2(Ap1_2, v, v);
    }

    int mi = lane >> 3, r8 = lane & 7;
    uint32_t b_row_off = ((mi >> 1) * 8 + r8) * (PSTR * 2) + (mi & 1) * 16;

    float d[8][4];
#pragma unroll
    for (int nb = 0; nb < 8; nb++)
#pragma unroll
        for (int q = 0; q < 4; q++) d[nb][q] = 0.f;
    float dsum[4] = {0.f, 0.f, 0.f, 0.f};

    uint2 awc0 = *(const uint2*)(bits0 + k0 * 2);
    uint2 awc1 = *(const uint2*)(bits1 + k0 * 2);
    uint2 awn0, awn1;

    for (int kk = 0; kk < 16; kk++) {
        int k = k0 + kk;
        CP_WAIT1();
        BARG(1 + g);
        if (kk < 15) {
            awn0 = *(const uint2*)(bits0 + (k + 1) * 2);
            awn1 = *(const uint2*)(bits1 + (k + 1) * 2);
        }
        uint32_t wb = wsh_u + (g * 3 + k % 3) * WTILE_B;
#pragma unroll
        for (int kc = 0; kc < 4; kc++) {
            uint32_t wA = (kc & 2) ? awc0.y : awc0.x;
            uint32_t wB = (kc & 2) ? awc1.y : awc1.x;
            int sh = ((kc & 1) << 4) + c2;
            int idx = (k * 64 + kc * 16 + c2) >> 1;
            uint2 u0 = cT[idx];          // pair (j, j+1)
            uint2 u1 = cT[idx + 4];      // pair (j+8, j+9)

            uint32_t ia0 = (wA >> sh) & 3u;
            uint32_t ia1 = (wA >> (sh + 8)) & 3u;
            uint32_t ib0 = (wB >> sh) & 3u;
            uint32_t ib1 = (wB >> (sh + 8)) & 3u;
            uint32_t mA0 = ((ia0 & 1u) ? 0x0000FFFFu : 0u) | ((ia0 & 2u) ? 0xFFFF0000u : 0u);
            uint32_t mA1 = ((ia1 & 1u) ? 0x0000FFFFu : 0u) | ((ia1 & 2u) ? 0xFFFF0000u : 0u);
            uint32_t mB0 = ((ib0 & 1u) ? 0x0000FFFFu : 0u) | ((ib0 & 2u) ? 0xFFFF0000u : 0u);
            uint32_t mB1 = ((ib1 & 1u) ? 0x0000FFFFu : 0u) | ((ib1 & 2u) ? 0xFFFF0000u : 0u);

            uint32_t x0, x1, fa0, fa1, fa2, fa3;
            HMUL2(x0, Ai0_2, u0.x); HMUL2(x1, Ap0_2, u0.y); HMAX2(fa0, x0, x1);
            HMUL2(x0, Ai1_2, u0.x); HMUL2(x1, Ap1_2, u0.y); HMAX2(fa1, x0, x1);
            HMUL2(x0, Ai0_2, u1.x); HMUL2(x1, Ap0_2, u1.y); HMAX2(fa2, x0, x1);
            HMUL2(x0, Ai1_2, u1.x); HMUL2(x1, Ap1_2, u1.y); HMAX2(fa3, x0, x1);
            fa0 &= mA0; fa1 &= mB0; fa2 &= mA1; fa3 &= mB1;

            MMA16816(dsum, fa0, fa1, fa2, fa3, ONE2, ONE2);
#pragma unroll
            for (int nbp = 0; nbp < 4; nbp++) {
                uint32_t q0, q1, q2, q3;
                LDSM4(q0, q1, q2, q3,
                      wb + nbp * 16 * (PSTR * 2) + b_row_off + kc * 32);
                MMA16816(d[nbp * 2],     fa0, fa1, fa2, fa3, q0, q1);
                MMA16816(d[nbp * 2 + 1], fa0, fa1, fa2, fa3, q2, q3);
            }
        }
        awc0 = awn0; awc1 = awn1;
        if (kk < 14) ISSUE_WH(k + 2);
        else CP_COMMIT();
    }

    // row sums from the ones-MMA: dsum[0] = row lr0, dsum[2] = row lr1
    float* rsg = g ? rs1 : rs0;
    if ((lane & 3) == 0) {
        rsg[lr0] = dsum[0];
        rsg[lr1] = dsum[2];
    }
    if (g) {
#pragma unroll
        for (int nb = 0; nb < 8; nb++)
#pragma unroll
            for (int q = 0; q < 4; q++)
                cbuf[(nb * 4 + q) * 256 + tl] = d[nb][q];
    }
    __syncthreads();

    if (g == 0) {
        float l0 = 1.0f / (rs0[lr0] + rs1[lr0]);
        float l1 = 1.0f / (rs0[lr1] + rs1[lr1]);
        float* o0 = out + (size_t)(b * Nn + i0 + lr0) * 64 + c2;
        float* o1 = out + (size_t)(b * Nn + i0 + lr1) * 64 + c2;
#pragma unroll
        for (int nb = 0; nb < 8; nb++) {
            float x0 = (d[nb][0] + cbuf[(nb * 4 + 0) * 256 + tl]) * l0;
            float x1 = (d[nb][1] + cbuf[(nb * 4 + 1) * 256 + tl]) * l0;
            float y0 = (d[nb][2] + cbuf[(nb * 4 + 2) * 256 + tl]) * l1;
            float y1 = (d[nb][3] + cbuf[(nb * 4 + 3) * 256 + tl]) * l1;
            float2 v0, v1;
            v0.x = x0 > 0.f ? x0 : expm1f(x0);
            v0.y = x1 > 0.f ? x1 : expm1f(x1);
            v1.x = y0 > 0.f ? y0 : expm1f(y0);
            v1.y = y1 > 0.f ? y1 : expm1f(y1);
            *(float2*)(o0 + nb * 8) = v0;
            *(float2*)(o1 + nb * 8) = v1;
        }
    }
}

// ---------------------------------------------------------------------------
extern "C" void kernel_launch(void* const* d_in, const int* in_sizes, int n_in,
                              void* d_out, int out_size) {
    const float* h   = (const float*)d_in[0];   // (8,2048,64) f32
    const int*   adj = (const int*)d_in[1];     // (8,2048,2048) i32
    const float* W   = (const float*)d_in[2];   // (64,64) f32
    const float* a   = (const float*)d_in[3];   // (128,1) f32
    float* out = (float*)d_out;                 // (8,2048,64) f32

    cudaFuncSetAttribute(kD, cudaFuncAttributeMaxDynamicSharedMemorySize, SMEM_TOT);

    kPA<<<2560, 256>>>(h, W, a, adj);
    kB<<<Bb, 256>>>();
    kD<<<dim3(Nn / 128, Bb), 512, SMEM_TOT>>>(out);
}